// round 2
// baseline (speedup 1.0000x reference)
#include <cuda_runtime.h>
#include <math.h>

#define BB 128   // batch
#define TT 128   // time steps
#define DD 1024  // hidden dim

// ---- scratch (device globals; no runtime allocation allowed) ----
__device__ float g_fWr[(size_t)BB * TT * DD];   // facts @ Wr^T  [b][t][k]
__device__ float g_fW [(size_t)BB * TT * DD];   // facts @ W^T   [b][t][k]
__device__ float g_h[2][BB * DD];               // ping-pong hidden state

// ============================================================
// Phase 1: C[m,k] = sum_d A[m,d] * Wt[k,d]   (both operands K-contiguous)
// A = facts [16384, 1024], Wt = Wr or W [1024, 1024]
// Tile 64x64x32, 256 threads, 4x4 per thread, float4 smem reads.
// ============================================================
__global__ __launch_bounds__(256) void phase1_kernel(
    const float* __restrict__ A,
    const float* __restrict__ Wr,
    const float* __restrict__ W)
{
    const float* Bw = (blockIdx.z == 0) ? Wr : W;
    float* C        = (blockIdx.z == 0) ? g_fWr : g_fW;

    const int m0 = blockIdx.x * 64;
    const int n0 = blockIdx.y * 64;

    __shared__ float As[32][68];  // [k][m], pad 68 (272B, 16B-aligned rows)
    __shared__ float Bs[32][68];  // [k][n]

    const int tid = threadIdx.x;
    const int tx  = tid & 15;   // n quad
    const int ty  = tid >> 4;   // m quad

    float acc[4][4] = {};

    for (int k0 = 0; k0 < DD; k0 += 32) {
        // load 64x32 A tile and 64x32 W tile, transposed into smem
        #pragma unroll
        for (int j = 0; j < 2; ++j) {
            int idx = tid + j * 256;       // 0..511 float4 slots
            int row = idx >> 3;            // 0..63
            int c4  = (idx & 7) * 4;       // 0..28
            float4 v = *(const float4*)(A  + (size_t)(m0 + row) * DD + k0 + c4);
            As[c4 + 0][row] = v.x; As[c4 + 1][row] = v.y;
            As[c4 + 2][row] = v.z; As[c4 + 3][row] = v.w;
            float4 w = *(const float4*)(Bw + (size_t)(n0 + row) * DD + k0 + c4);
            Bs[c4 + 0][row] = w.x; Bs[c4 + 1][row] = w.y;
            Bs[c4 + 2][row] = w.z; Bs[c4 + 3][row] = w.w;
        }
        __syncthreads();

        #pragma unroll
        for (int kk = 0; kk < 32; ++kk) {
            float4 a = *(const float4*)&As[kk][ty * 4];
            float4 b = *(const float4*)&Bs[kk][tx * 4];
            float av[4] = {a.x, a.y, a.z, a.w};
            float bv[4] = {b.x, b.y, b.z, b.w};
            #pragma unroll
            for (int i = 0; i < 4; ++i)
                #pragma unroll
                for (int j = 0; j < 4; ++j)
                    acc[i][j] += av[i] * bv[j];
        }
        __syncthreads();
    }

    #pragma unroll
    for (int i = 0; i < 4; ++i) {
        float4 v = make_float4(acc[i][0], acc[i][1], acc[i][2], acc[i][3]);
        *(float4*)(C + (size_t)(m0 + ty * 4 + i) * DD + n0 + tx * 4) = v;
    }
}

// ============================================================
// init: h[0] = mem_old  (B x D)
// ============================================================
__global__ void init_h_kernel(const float* __restrict__ mem_old)
{
    int i = blockIdx.x * blockDim.x + threadIdx.x;
    if (i < BB * DD) g_h[0][i] = mem_old[i];
}

// ============================================================
// Phase 2 step t:
//   accR[b,n] = sum_d h[b,d]*Ur_w[n,d];  accU[b,n] = sum_d h[b,d]*U_w[n,d]
//   r  = sigmoid(fWr[b,t,n] + accR + Ur_b[n])
//   ht = tanh   (fW [b,t,n] + r*(accU + U_b[n]))
//   hn = g[b,t]*ht + (1-g[b,t])*h[b,n]
//   h_out = hn; if (num_facts[b]-1 == t) out[b,n] = hn
// Tile 32(batch) x 32(feat) x 32(k), 256 threads, 2x2 per thread, dual acc.
// Grid 4 x 32 = 128 blocks.
// ============================================================
__global__ __launch_bounds__(256) void step_kernel(
    int t,
    const float* __restrict__ g,
    const int*   __restrict__ num_facts,
    const float* __restrict__ Ur_w, const float* __restrict__ Ur_b,
    const float* __restrict__ U_w,  const float* __restrict__ U_b,
    float* __restrict__ out)
{
    const float* h_in  = g_h[t & 1];
    float*       h_out = g_h[(t & 1) ^ 1];

    const int m0 = blockIdx.x * 32;   // batch
    const int n0 = blockIdx.y * 32;   // feature

    __shared__ float Hs[32][34];      // [k][b]  pad 34 (136B rows, 8B aligned)
    __shared__ float Rs[32][34];      // [k][n] for Ur_w
    __shared__ float Us[32][34];      // [k][n] for U_w

    const int tid = threadIdx.x;
    const int tx  = tid & 15;   // n pair
    const int ty  = tid >> 4;   // b pair

    float accR[2][2] = {};
    float accU[2][2] = {};

    const int row = tid >> 3;          // 0..31
    const int c4  = (tid & 7) * 4;     // 0..28

    for (int k0 = 0; k0 < DD; k0 += 32) {
        float4 hv = *(const float4*)(h_in + (size_t)(m0 + row) * DD + k0 + c4);
        Hs[c4 + 0][row] = hv.x; Hs[c4 + 1][row] = hv.y;
        Hs[c4 + 2][row] = hv.z; Hs[c4 + 3][row] = hv.w;
        float4 rv = *(const float4*)(Ur_w + (size_t)(n0 + row) * DD + k0 + c4);
        Rs[c4 + 0][row] = rv.x; Rs[c4 + 1][row] = rv.y;
        Rs[c4 + 2][row] = rv.z; Rs[c4 + 3][row] = rv.w;
        float4 uv = *(const float4*)(U_w + (size_t)(n0 + row) * DD + k0 + c4);
        Us[c4 + 0][row] = uv.x; Us[c4 + 1][row] = uv.y;
        Us[c4 + 2][row] = uv.z; Us[c4 + 3][row] = uv.w;
        __syncthreads();

        #pragma unroll
        for (int kk = 0; kk < 32; ++kk) {
            float2 a  = *(const float2*)&Hs[kk][ty * 2];
            float2 br = *(const float2*)&Rs[kk][tx * 2];
            float2 bu = *(const float2*)&Us[kk][tx * 2];
            accR[0][0] += a.x * br.x;  accR[0][1] += a.x * br.y;
            accR[1][0] += a.y * br.x;  accR[1][1] += a.y * br.y;
            accU[0][0] += a.x * bu.x;  accU[0][1] += a.x * bu.y;
            accU[1][0] += a.y * bu.x;  accU[1][1] += a.y * bu.y;
        }
        __syncthreads();
    }

    #pragma unroll
    for (int i = 0; i < 2; ++i) {
        int b = m0 + ty * 2 + i;
        float gv   = g[b * TT + t];
        int   last = (num_facts[b] - 1 == t);
        #pragma unroll
        for (int j = 0; j < 2; ++j) {
            int n = n0 + tx * 2 + j;
            size_t ft_idx = ((size_t)b * TT + t) * DD + n;
            float fwr = g_fWr[ft_idx];
            float fw  = g_fW [ft_idx];
            float r  = 1.0f / (1.0f + __expf(-(accR[i][j] + fwr + Ur_b[n])));
            float ht = tanhf(fw + r * (accU[i][j] + U_b[n]));
            float hp = h_in[(size_t)b * DD + n];
            float hn = gv * ht + (1.0f - gv) * hp;
            h_out[(size_t)b * DD + n] = hn;
            if (last) out[(size_t)b * DD + n] = hn;
        }
    }
}

// ============================================================
extern "C" void kernel_launch(void* const* d_in, const int* in_sizes, int n_in,
                              void* d_out, int out_size)
{
    const float* facts     = (const float*)d_in[0];
    const int*   num_facts = (const int*)  d_in[1];
    const float* g         = (const float*)d_in[2];
    const float* mem_old   = (const float*)d_in[3];
    const float* Wr        = (const float*)d_in[4];
    const float* Ur_w      = (const float*)d_in[5];
    const float* Ur_b      = (const float*)d_in[6];
    const float* W         = (const float*)d_in[7];
    const float* U_w       = (const float*)d_in[8];
    const float* U_b       = (const float*)d_in[9];
    float*       out       = (float*)d_out;

    (void)in_sizes; (void)n_in; (void)out_size;

    // Phase 1: both big GEMMs (fWr, fW) — grid.z selects weight/output pair
    phase1_kernel<<<dim3((BB * TT) / 64, DD / 64, 2), 256>>>(facts, Wr, W);

    // init hidden state
    init_h_kernel<<<(BB * DD + 255) / 256, 256>>>(mem_old);

    // Phase 2: sequential scan, one fused kernel per step
    for (int t = 0; t < TT; ++t) {
        step_kernel<<<dim3(BB / 32, DD / 32), 256>>>(
            t, g, num_facts, Ur_w, Ur_b, U_w, U_b, out);
    }
}

// round 3
// speedup vs baseline: 1.0001x; 1.0001x over previous
#include <cuda_runtime.h>
#include <math.h>

#define BB 128   // batch
#define TT 128   // time steps
#define DD 1024  // hidden dim

// ---- scratch (device globals; no runtime allocation allowed) ----
__device__ float g_fWr[(size_t)BB * TT * DD];   // facts @ Wr^T  [b][t][k]
__device__ float g_fW [(size_t)BB * TT * DD];   // facts @ W^T   [b][t][k]
__device__ float g_h[2][BB * DD];               // ping-pong hidden state

// ============================================================
// Phase 1: C[m,k] = sum_d A[m,d] * Wt[k,d]   (both operands K-contiguous)
// A = facts [16384, 1024], Wt = Wr or W [1024, 1024]
// Tile 64x64x32, 256 threads, 4x4 per thread, float4 smem reads.
// ============================================================
__global__ __launch_bounds__(256) void phase1_kernel(
    const float* __restrict__ A,
    const float* __restrict__ Wr,
    const float* __restrict__ W)
{
    const float* Bw = (blockIdx.z == 0) ? Wr : W;
    float* C        = (blockIdx.z == 0) ? g_fWr : g_fW;

    const int m0 = blockIdx.x * 64;
    const int n0 = blockIdx.y * 64;

    __shared__ float As[32][68];  // [k][m], pad 68 (272B, 16B-aligned rows)
    __shared__ float Bs[32][68];  // [k][n]

    const int tid = threadIdx.x;
    const int tx  = tid & 15;   // n quad
    const int ty  = tid >> 4;   // m quad

    float acc[4][4] = {};

    for (int k0 = 0; k0 < DD; k0 += 32) {
        // load 64x32 A tile and 64x32 W tile, transposed into smem
        #pragma unroll
        for (int j = 0; j < 2; ++j) {
            int idx = tid + j * 256;       // 0..511 float4 slots
            int row = idx >> 3;            // 0..63
            int c4  = (idx & 7) * 4;       // 0..28
            float4 v = *(const float4*)(A  + (size_t)(m0 + row) * DD + k0 + c4);
            As[c4 + 0][row] = v.x; As[c4 + 1][row] = v.y;
            As[c4 + 2][row] = v.z; As[c4 + 3][row] = v.w;
            float4 w = *(const float4*)(Bw + (size_t)(n0 + row) * DD + k0 + c4);
            Bs[c4 + 0][row] = w.x; Bs[c4 + 1][row] = w.y;
            Bs[c4 + 2][row] = w.z; Bs[c4 + 3][row] = w.w;
        }
        __syncthreads();

        #pragma unroll
        for (int kk = 0; kk < 32; ++kk) {
            float4 a = *(const float4*)&As[kk][ty * 4];
            float4 b = *(const float4*)&Bs[kk][tx * 4];
            float av[4] = {a.x, a.y, a.z, a.w};
            float bv[4] = {b.x, b.y, b.z, b.w};
            #pragma unroll
            for (int i = 0; i < 4; ++i)
                #pragma unroll
                for (int j = 0; j < 4; ++j)
                    acc[i][j] += av[i] * bv[j];
        }
        __syncthreads();
    }

    #pragma unroll
    for (int i = 0; i < 4; ++i) {
        float4 v = make_float4(acc[i][0], acc[i][1], acc[i][2], acc[i][3]);
        *(float4*)(C + (size_t)(m0 + ty * 4 + i) * DD + n0 + tx * 4) = v;
    }
}

// ============================================================
// init: h[0] = mem_old  (B x D)
// ============================================================
__global__ void init_h_kernel(const float* __restrict__ mem_old)
{
    int i = blockIdx.x * blockDim.x + threadIdx.x;
    if (i < BB * DD) g_h[0][i] = mem_old[i];
}

// ============================================================
// Phase 2 step t:
//   accR[b,n] = sum_d h[b,d]*Ur_w[n,d];  accU[b,n] = sum_d h[b,d]*U_w[n,d]
//   r  = sigmoid(fWr[b,t,n] + accR + Ur_b[n])
//   ht = tanh   (fW [b,t,n] + r*(accU + U_b[n]))
//   hn = g[b,t]*ht + (1-g[b,t])*h[b,n]
//   h_out = hn; if (num_facts[b]-1 == t) out[b,n] = hn
// Tile 32(batch) x 32(feat) x 32(k), 256 threads, 2x2 per thread, dual acc.
// Grid 4 x 32 = 128 blocks.
// ============================================================
__global__ __launch_bounds__(256) void step_kernel(
    int t,
    const float* __restrict__ g,
    const int*   __restrict__ num_facts,
    const float* __restrict__ Ur_w, const float* __restrict__ Ur_b,
    const float* __restrict__ U_w,  const float* __restrict__ U_b,
    float* __restrict__ out)
{
    const float* h_in  = g_h[t & 1];
    float*       h_out = g_h[(t & 1) ^ 1];

    const int m0 = blockIdx.x * 32;   // batch
    const int n0 = blockIdx.y * 32;   // feature

    __shared__ float Hs[32][34];      // [k][b]  pad 34 (136B rows, 8B aligned)
    __shared__ float Rs[32][34];      // [k][n] for Ur_w
    __shared__ float Us[32][34];      // [k][n] for U_w

    const int tid = threadIdx.x;
    const int tx  = tid & 15;   // n pair
    const int ty  = tid >> 4;   // b pair

    float accR[2][2] = {};
    float accU[2][2] = {};

    const int row = tid >> 3;          // 0..31
    const int c4  = (tid & 7) * 4;     // 0..28

    for (int k0 = 0; k0 < DD; k0 += 32) {
        float4 hv = *(const float4*)(h_in + (size_t)(m0 + row) * DD + k0 + c4);
        Hs[c4 + 0][row] = hv.x; Hs[c4 + 1][row] = hv.y;
        Hs[c4 + 2][row] = hv.z; Hs[c4 + 3][row] = hv.w;
        float4 rv = *(const float4*)(Ur_w + (size_t)(n0 + row) * DD + k0 + c4);
        Rs[c4 + 0][row] = rv.x; Rs[c4 + 1][row] = rv.y;
        Rs[c4 + 2][row] = rv.z; Rs[c4 + 3][row] = rv.w;
        float4 uv = *(const float4*)(U_w + (size_t)(n0 + row) * DD + k0 + c4);
        Us[c4 + 0][row] = uv.x; Us[c4 + 1][row] = uv.y;
        Us[c4 + 2][row] = uv.z; Us[c4 + 3][row] = uv.w;
        __syncthreads();

        #pragma unroll
        for (int kk = 0; kk < 32; ++kk) {
            float2 a  = *(const float2*)&Hs[kk][ty * 2];
            float2 br = *(const float2*)&Rs[kk][tx * 2];
            float2 bu = *(const float2*)&Us[kk][tx * 2];
            accR[0][0] += a.x * br.x;  accR[0][1] += a.x * br.y;
            accR[1][0] += a.y * br.x;  accR[1][1] += a.y * br.y;
            accU[0][0] += a.x * bu.x;  accU[0][1] += a.x * bu.y;
            accU[1][0] += a.y * bu.x;  accU[1][1] += a.y * bu.y;
        }
        __syncthreads();
    }

    #pragma unroll
    for (int i = 0; i < 2; ++i) {
        int b = m0 + ty * 2 + i;
        float gv   = g[b * TT + t];
        int   last = (num_facts[b] - 1 == t);
        #pragma unroll
        for (int j = 0; j < 2; ++j) {
            int n = n0 + tx * 2 + j;
            size_t ft_idx = ((size_t)b * TT + t) * DD + n;
            float fwr = g_fWr[ft_idx];
            float fw  = g_fW [ft_idx];
            float r  = 1.0f / (1.0f + __expf(-(accR[i][j] + fwr + Ur_b[n])));
            float ht = tanhf(fw + r * (accU[i][j] + U_b[n]));
            float hp = h_in[(size_t)b * DD + n];
            float hn = gv * ht + (1.0f - gv) * hp;
            h_out[(size_t)b * DD + n] = hn;
            if (last) out[(size_t)b * DD + n] = hn;
        }
    }
}

// ============================================================
extern "C" void kernel_launch(void* const* d_in, const int* in_sizes, int n_in,
                              void* d_out, int out_size)
{
    const float* facts     = (const float*)d_in[0];
    const int*   num_facts = (const int*)  d_in[1];
    const float* g         = (const float*)d_in[2];
    const float* mem_old   = (const float*)d_in[3];
    const float* Wr        = (const float*)d_in[4];
    const float* Ur_w      = (const float*)d_in[5];
    const float* Ur_b      = (const float*)d_in[6];
    const float* W         = (const float*)d_in[7];
    const float* U_w       = (const float*)d_in[8];
    const float* U_b       = (const float*)d_in[9];
    float*       out       = (float*)d_out;

    (void)in_sizes; (void)n_in; (void)out_size;

    // Phase 1: both big GEMMs (fWr, fW) — grid.z selects weight/output pair
    phase1_kernel<<<dim3((BB * TT) / 64, DD / 64, 2), 256>>>(facts, Wr, W);

    // init hidden state
    init_h_kernel<<<(BB * DD + 255) / 256, 256>>>(mem_old);

    // Phase 2: sequential scan, one fused kernel per step
    for (int t = 0; t < TT; ++t) {
        step_kernel<<<dim3(BB / 32, DD / 32), 256>>>(
            t, g, num_facts, Ur_w, Ur_b, U_w, U_b, out);
    }
}

// round 4
// speedup vs baseline: 1.0003x; 1.0003x over previous
#include <cuda_runtime.h>
#include <math.h>

#define BB 128   // batch
#define TT 128   // time steps
#define DD 1024  // hidden dim

// ---- scratch (device globals; no runtime allocation allowed) ----
__device__ float g_fWr[(size_t)BB * TT * DD];   // facts @ Wr^T  [b][t][k]
__device__ float g_fW [(size_t)BB * TT * DD];   // facts @ W^T   [b][t][k]
__device__ float g_h[2][BB * DD];               // ping-pong hidden state

// ============================================================
// Phase 1: C[m,k] = sum_d A[m,d] * Wt[k,d]   (both operands K-contiguous)
// A = facts [16384, 1024], Wt = Wr or W [1024, 1024]
// Tile 64x64x32, 256 threads, 4x4 per thread, float4 smem reads.
// ============================================================
__global__ __launch_bounds__(256) void phase1_kernel(
    const float* __restrict__ A,
    const float* __restrict__ Wr,
    const float* __restrict__ W)
{
    const float* Bw = (blockIdx.z == 0) ? Wr : W;
    float* C        = (blockIdx.z == 0) ? g_fWr : g_fW;

    const int m0 = blockIdx.x * 64;
    const int n0 = blockIdx.y * 64;

    __shared__ float As[32][68];  // [k][m], pad 68 (272B, 16B-aligned rows)
    __shared__ float Bs[32][68];  // [k][n]

    const int tid = threadIdx.x;
    const int tx  = tid & 15;   // n quad
    const int ty  = tid >> 4;   // m quad

    float acc[4][4] = {};

    for (int k0 = 0; k0 < DD; k0 += 32) {
        // load 64x32 A tile and 64x32 W tile, transposed into smem
        #pragma unroll
        for (int j = 0; j < 2; ++j) {
            int idx = tid + j * 256;       // 0..511 float4 slots
            int row = idx >> 3;            // 0..63
            int c4  = (idx & 7) * 4;       // 0..28
            float4 v = *(const float4*)(A  + (size_t)(m0 + row) * DD + k0 + c4);
            As[c4 + 0][row] = v.x; As[c4 + 1][row] = v.y;
            As[c4 + 2][row] = v.z; As[c4 + 3][row] = v.w;
            float4 w = *(const float4*)(Bw + (size_t)(n0 + row) * DD + k0 + c4);
            Bs[c4 + 0][row] = w.x; Bs[c4 + 1][row] = w.y;
            Bs[c4 + 2][row] = w.z; Bs[c4 + 3][row] = w.w;
        }
        __syncthreads();

        #pragma unroll
        for (int kk = 0; kk < 32; ++kk) {
            float4 a = *(const float4*)&As[kk][ty * 4];
            float4 b = *(const float4*)&Bs[kk][tx * 4];
            float av[4] = {a.x, a.y, a.z, a.w};
            float bv[4] = {b.x, b.y, b.z, b.w};
            #pragma unroll
            for (int i = 0; i < 4; ++i)
                #pragma unroll
                for (int j = 0; j < 4; ++j)
                    acc[i][j] += av[i] * bv[j];
        }
        __syncthreads();
    }

    #pragma unroll
    for (int i = 0; i < 4; ++i) {
        float4 v = make_float4(acc[i][0], acc[i][1], acc[i][2], acc[i][3]);
        *(float4*)(C + (size_t)(m0 + ty * 4 + i) * DD + n0 + tx * 4) = v;
    }
}

// ============================================================
// init: h[0] = mem_old  (B x D)
// ============================================================
__global__ void init_h_kernel(const float* __restrict__ mem_old)
{
    int i = blockIdx.x * blockDim.x + threadIdx.x;
    if (i < BB * DD) g_h[0][i] = mem_old[i];
}

// ============================================================
// Phase 2 step t:
//   accR[b,n] = sum_d h[b,d]*Ur_w[n,d];  accU[b,n] = sum_d h[b,d]*U_w[n,d]
//   r  = sigmoid(fWr[b,t,n] + accR + Ur_b[n])
//   ht = tanh   (fW [b,t,n] + r*(accU + U_b[n]))
//   hn = g[b,t]*ht + (1-g[b,t])*h[b,n]
//   h_out = hn; if (num_facts[b]-1 == t) out[b,n] = hn
// Tile 32(batch) x 32(feat) x 32(k), 256 threads, 2x2 per thread, dual acc.
// Grid 4 x 32 = 128 blocks.
// ============================================================
__global__ __launch_bounds__(256) void step_kernel(
    int t,
    const float* __restrict__ g,
    const int*   __restrict__ num_facts,
    const float* __restrict__ Ur_w, const float* __restrict__ Ur_b,
    const float* __restrict__ U_w,  const float* __restrict__ U_b,
    float* __restrict__ out)
{
    const float* h_in  = g_h[t & 1];
    float*       h_out = g_h[(t & 1) ^ 1];

    const int m0 = blockIdx.x * 32;   // batch
    const int n0 = blockIdx.y * 32;   // feature

    __shared__ float Hs[32][34];      // [k][b]  pad 34 (136B rows, 8B aligned)
    __shared__ float Rs[32][34];      // [k][n] for Ur_w
    __shared__ float Us[32][34];      // [k][n] for U_w

    const int tid = threadIdx.x;
    const int tx  = tid & 15;   // n pair
    const int ty  = tid >> 4;   // b pair

    float accR[2][2] = {};
    float accU[2][2] = {};

    const int row = tid >> 3;          // 0..31
    const int c4  = (tid & 7) * 4;     // 0..28

    for (int k0 = 0; k0 < DD; k0 += 32) {
        float4 hv = *(const float4*)(h_in + (size_t)(m0 + row) * DD + k0 + c4);
        Hs[c4 + 0][row] = hv.x; Hs[c4 + 1][row] = hv.y;
        Hs[c4 + 2][row] = hv.z; Hs[c4 + 3][row] = hv.w;
        float4 rv = *(const float4*)(Ur_w + (size_t)(n0 + row) * DD + k0 + c4);
        Rs[c4 + 0][row] = rv.x; Rs[c4 + 1][row] = rv.y;
        Rs[c4 + 2][row] = rv.z; Rs[c4 + 3][row] = rv.w;
        float4 uv = *(const float4*)(U_w + (size_t)(n0 + row) * DD + k0 + c4);
        Us[c4 + 0][row] = uv.x; Us[c4 + 1][row] = uv.y;
        Us[c4 + 2][row] = uv.z; Us[c4 + 3][row] = uv.w;
        __syncthreads();

        #pragma unroll
        for (int kk = 0; kk < 32; ++kk) {
            float2 a  = *(const float2*)&Hs[kk][ty * 2];
            float2 br = *(const float2*)&Rs[kk][tx * 2];
            float2 bu = *(const float2*)&Us[kk][tx * 2];
            accR[0][0] += a.x * br.x;  accR[0][1] += a.x * br.y;
            accR[1][0] += a.y * br.x;  accR[1][1] += a.y * br.y;
            accU[0][0] += a.x * bu.x;  accU[0][1] += a.x * bu.y;
            accU[1][0] += a.y * bu.x;  accU[1][1] += a.y * bu.y;
        }
        __syncthreads();
    }

    #pragma unroll
    for (int i = 0; i < 2; ++i) {
        int b = m0 + ty * 2 + i;
        float gv   = g[b * TT + t];
        int   last = (num_facts[b] - 1 == t);
        #pragma unroll
        for (int j = 0; j < 2; ++j) {
            int n = n0 + tx * 2 + j;
            size_t ft_idx = ((size_t)b * TT + t) * DD + n;
            float fwr = g_fWr[ft_idx];
            float fw  = g_fW [ft_idx];
            float r  = 1.0f / (1.0f + __expf(-(accR[i][j] + fwr + Ur_b[n])));
            float ht = tanhf(fw + r * (accU[i][j] + U_b[n]));
            float hp = h_in[(size_t)b * DD + n];
            float hn = gv * ht + (1.0f - gv) * hp;
            h_out[(size_t)b * DD + n] = hn;
            if (last) out[(size_t)b * DD + n] = hn;
        }
    }
}

// ============================================================
extern "C" void kernel_launch(void* const* d_in, const int* in_sizes, int n_in,
                              void* d_out, int out_size)
{
    const float* facts     = (const float*)d_in[0];
    const int*   num_facts = (const int*)  d_in[1];
    const float* g         = (const float*)d_in[2];
    const float* mem_old   = (const float*)d_in[3];
    const float* Wr        = (const float*)d_in[4];
    const float* Ur_w      = (const float*)d_in[5];
    const float* Ur_b      = (const float*)d_in[6];
    const float* W         = (const float*)d_in[7];
    const float* U_w       = (const float*)d_in[8];
    const float* U_b       = (const float*)d_in[9];
    float*       out       = (float*)d_out;

    (void)in_sizes; (void)n_in; (void)out_size;

    // Phase 1: both big GEMMs (fWr, fW) — grid.z selects weight/output pair
    phase1_kernel<<<dim3((BB * TT) / 64, DD / 64, 2), 256>>>(facts, Wr, W);

    // init hidden state
    init_h_kernel<<<(BB * DD + 255) / 256, 256>>>(mem_old);

    // Phase 2: sequential scan, one fused kernel per step
    for (int t = 0; t < TT; ++t) {
        step_kernel<<<dim3(BB / 32, DD / 32), 256>>>(
            t, g, num_facts, Ur_w, Ur_b, U_w, U_b, out);
    }
}

// round 5
// speedup vs baseline: 1.0004x; 1.0000x over previous
#include <cuda_runtime.h>
#include <math.h>

#define BB 128   // batch
#define TT 128   // time steps
#define DD 1024  // hidden dim

// ---- scratch (device globals; no runtime allocation allowed) ----
__device__ float g_fWr[(size_t)BB * TT * DD];   // facts @ Wr^T  [b][t][k]
__device__ float g_fW [(size_t)BB * TT * DD];   // facts @ W^T   [b][t][k]
__device__ float g_h[2][BB * DD];               // ping-pong hidden state

// ============================================================
// Phase 1: C[m,k] = sum_d A[m,d] * Wt[k,d]   (both operands K-contiguous)
// A = facts [16384, 1024], Wt = Wr or W [1024, 1024]
// Tile 64x64x32, 256 threads, 4x4 per thread, float4 smem reads.
// ============================================================
__global__ __launch_bounds__(256) void phase1_kernel(
    const float* __restrict__ A,
    const float* __restrict__ Wr,
    const float* __restrict__ W)
{
    const float* Bw = (blockIdx.z == 0) ? Wr : W;
    float* C        = (blockIdx.z == 0) ? g_fWr : g_fW;

    const int m0 = blockIdx.x * 64;
    const int n0 = blockIdx.y * 64;

    __shared__ float As[32][68];  // [k][m], pad 68 (272B, 16B-aligned rows)
    __shared__ float Bs[32][68];  // [k][n]

    const int tid = threadIdx.x;
    const int tx  = tid & 15;   // n quad
    const int ty  = tid >> 4;   // m quad

    float acc[4][4] = {};

    for (int k0 = 0; k0 < DD; k0 += 32) {
        // load 64x32 A tile and 64x32 W tile, transposed into smem
        #pragma unroll
        for (int j = 0; j < 2; ++j) {
            int idx = tid + j * 256;       // 0..511 float4 slots
            int row = idx >> 3;            // 0..63
            int c4  = (idx & 7) * 4;       // 0..28
            float4 v = *(const float4*)(A  + (size_t)(m0 + row) * DD + k0 + c4);
            As[c4 + 0][row] = v.x; As[c4 + 1][row] = v.y;
            As[c4 + 2][row] = v.z; As[c4 + 3][row] = v.w;
            float4 w = *(const float4*)(Bw + (size_t)(n0 + row) * DD + k0 + c4);
            Bs[c4 + 0][row] = w.x; Bs[c4 + 1][row] = w.y;
            Bs[c4 + 2][row] = w.z; Bs[c4 + 3][row] = w.w;
        }
        __syncthreads();

        #pragma unroll
        for (int kk = 0; kk < 32; ++kk) {
            float4 a = *(const float4*)&As[kk][ty * 4];
            float4 b = *(const float4*)&Bs[kk][tx * 4];
            float av[4] = {a.x, a.y, a.z, a.w};
            float bv[4] = {b.x, b.y, b.z, b.w};
            #pragma unroll
            for (int i = 0; i < 4; ++i)
                #pragma unroll
                for (int j = 0; j < 4; ++j)
                    acc[i][j] += av[i] * bv[j];
        }
        __syncthreads();
    }

    #pragma unroll
    for (int i = 0; i < 4; ++i) {
        float4 v = make_float4(acc[i][0], acc[i][1], acc[i][2], acc[i][3]);
        *(float4*)(C + (size_t)(m0 + ty * 4 + i) * DD + n0 + tx * 4) = v;
    }
}

// ============================================================
// init: h[0] = mem_old  (B x D)
// ============================================================
__global__ void init_h_kernel(const float* __restrict__ mem_old)
{
    int i = blockIdx.x * blockDim.x + threadIdx.x;
    if (i < BB * DD) g_h[0][i] = mem_old[i];
}

// ============================================================
// Phase 2 step t:
//   accR[b,n] = sum_d h[b,d]*Ur_w[n,d];  accU[b,n] = sum_d h[b,d]*U_w[n,d]
//   r  = sigmoid(fWr[b,t,n] + accR + Ur_b[n])
//   ht = tanh   (fW [b,t,n] + r*(accU + U_b[n]))
//   hn = g[b,t]*ht + (1-g[b,t])*h[b,n]
//   h_out = hn; if (num_facts[b]-1 == t) out[b,n] = hn
// Tile 32(batch) x 32(feat) x 32(k), 256 threads, 2x2 per thread, dual acc.
// Grid 4 x 32 = 128 blocks.
// ============================================================
__global__ __launch_bounds__(256) void step_kernel(
    int t,
    const float* __restrict__ g,
    const int*   __restrict__ num_facts,
    const float* __restrict__ Ur_w, const float* __restrict__ Ur_b,
    const float* __restrict__ U_w,  const float* __restrict__ U_b,
    float* __restrict__ out)
{
    const float* h_in  = g_h[t & 1];
    float*       h_out = g_h[(t & 1) ^ 1];

    const int m0 = blockIdx.x * 32;   // batch
    const int n0 = blockIdx.y * 32;   // feature

    __shared__ float Hs[32][34];      // [k][b]  pad 34 (136B rows, 8B aligned)
    __shared__ float Rs[32][34];      // [k][n] for Ur_w
    __shared__ float Us[32][34];      // [k][n] for U_w

    const int tid = threadIdx.x;
    const int tx  = tid & 15;   // n pair
    const int ty  = tid >> 4;   // b pair

    float accR[2][2] = {};
    float accU[2][2] = {};

    const int row = tid >> 3;          // 0..31
    const int c4  = (tid & 7) * 4;     // 0..28

    for (int k0 = 0; k0 < DD; k0 += 32) {
        float4 hv = *(const float4*)(h_in + (size_t)(m0 + row) * DD + k0 + c4);
        Hs[c4 + 0][row] = hv.x; Hs[c4 + 1][row] = hv.y;
        Hs[c4 + 2][row] = hv.z; Hs[c4 + 3][row] = hv.w;
        float4 rv = *(const float4*)(Ur_w + (size_t)(n0 + row) * DD + k0 + c4);
        Rs[c4 + 0][row] = rv.x; Rs[c4 + 1][row] = rv.y;
        Rs[c4 + 2][row] = rv.z; Rs[c4 + 3][row] = rv.w;
        float4 uv = *(const float4*)(U_w + (size_t)(n0 + row) * DD + k0 + c4);
        Us[c4 + 0][row] = uv.x; Us[c4 + 1][row] = uv.y;
        Us[c4 + 2][row] = uv.z; Us[c4 + 3][row] = uv.w;
        __syncthreads();

        #pragma unroll
        for (int kk = 0; kk < 32; ++kk) {
            float2 a  = *(const float2*)&Hs[kk][ty * 2];
            float2 br = *(const float2*)&Rs[kk][tx * 2];
            float2 bu = *(const float2*)&Us[kk][tx * 2];
            accR[0][0] += a.x * br.x;  accR[0][1] += a.x * br.y;
            accR[1][0] += a.y * br.x;  accR[1][1] += a.y * br.y;
            accU[0][0] += a.x * bu.x;  accU[0][1] += a.x * bu.y;
            accU[1][0] += a.y * bu.x;  accU[1][1] += a.y * bu.y;
        }
        __syncthreads();
    }

    #pragma unroll
    for (int i = 0; i < 2; ++i) {
        int b = m0 + ty * 2 + i;
        float gv   = g[b * TT + t];
        int   last = (num_facts[b] - 1 == t);
        #pragma unroll
        for (int j = 0; j < 2; ++j) {
            int n = n0 + tx * 2 + j;
            size_t ft_idx = ((size_t)b * TT + t) * DD + n;
            float fwr = g_fWr[ft_idx];
            float fw  = g_fW [ft_idx];
            float r  = 1.0f / (1.0f + __expf(-(accR[i][j] + fwr + Ur_b[n])));
            float ht = tanhf(fw + r * (accU[i][j] + U_b[n]));
            float hp = h_in[(size_t)b * DD + n];
            float hn = gv * ht + (1.0f - gv) * hp;
            h_out[(size_t)b * DD + n] = hn;
            if (last) out[(size_t)b * DD + n] = hn;
        }
    }
}

// ============================================================
extern "C" void kernel_launch(void* const* d_in, const int* in_sizes, int n_in,
                              void* d_out, int out_size)
{
    const float* facts     = (const float*)d_in[0];
    const int*   num_facts = (const int*)  d_in[1];
    const float* g         = (const float*)d_in[2];
    const float* mem_old   = (const float*)d_in[3];
    const float* Wr        = (const float*)d_in[4];
    const float* Ur_w      = (const float*)d_in[5];
    const float* Ur_b      = (const float*)d_in[6];
    const float* W         = (const float*)d_in[7];
    const float* U_w       = (const float*)d_in[8];
    const float* U_b       = (const float*)d_in[9];
    float*       out       = (float*)d_out;

    (void)in_sizes; (void)n_in; (void)out_size;

    // Phase 1: both big GEMMs (fWr, fW) — grid.z selects weight/output pair
    phase1_kernel<<<dim3((BB * TT) / 64, DD / 64, 2), 256>>>(facts, Wr, W);

    // init hidden state
    init_h_kernel<<<(BB * DD + 255) / 256, 256>>>(mem_old);

    // Phase 2: sequential scan, one fused kernel per step
    for (int t = 0; t < TT; ++t) {
        step_kernel<<<dim3(BB / 32, DD / 32), 256>>>(
            t, g, num_facts, Ur_w, Ur_b, U_w, U_b, out);
    }
}